// round 1
// baseline (speedup 1.0000x reference)
#include <cuda_runtime.h>
#include <float.h>

#define BB 4
#define NR 180
#define CC 512
#define HH 48
#define WW 48
#define F_IN 2048
#define OO 64
#define EPSV 1e-5f

// ---------------- device scratch (no allocations allowed) ----------------
__device__ float d_feat_t[BB * HH * WW * CC];   // [B,H,W,C]  ~18.9MB
__device__ float d_pooled[BB * NR * F_IN];      // relu'd pooled  ~5.9MB
__device__ float d_W1t[F_IN * OO];              // W1 transposed [F,O]
__device__ float d_Wsum[OO];                    // sum_f W1[o,f]
__device__ float d_a1[NR];                      // gamma1*rsqrt(var1+eps)
__device__ float d_c1[NR];                      // beta1 - a1*mean1
__device__ float d_g[BB * NR * OO];             // raw GEMM result

// ---------------- K1: features [B,C,H,W] -> [B,H,W,C] ----------------
__global__ void k_transpose(const float* __restrict__ feat) {
    __shared__ float tile[32][33];
    int bh = blockIdx.z;            // b*H + h
    int b = bh / HH, h = bh % HH;
    int c0 = blockIdx.y * 32;
    int w0 = blockIdx.x * 32;
    // read coalesced in w
    #pragma unroll
    for (int k = 0; k < 32; k += 8) {
        int c = c0 + threadIdx.y + k;
        int w = w0 + threadIdx.x;
        if (w < WW)
            tile[threadIdx.y + k][threadIdx.x] = feat[((b * CC + c) * HH + h) * WW + w];
    }
    __syncthreads();
    // write coalesced in c
    #pragma unroll
    for (int k = 0; k < 32; k += 8) {
        int w = w0 + threadIdx.y + k;
        int c = c0 + threadIdx.x;
        if (w < WW)
            d_feat_t[(bh * WW + w) * CC + c] = tile[threadIdx.x][threadIdx.y + k];
    }
}

// ---------------- K2: W1 transpose + row sums ----------------
__global__ void k_prep_w1(const float* __restrict__ W1) {
    int o = blockIdx.x;     // 64 blocks, 256 threads
    float s = 0.f;
    for (int f = threadIdx.x; f < F_IN; f += 256) {
        float v = W1[o * F_IN + f];
        d_W1t[f * OO + o] = v;
        s += v;
    }
    __shared__ float red[256];
    red[threadIdx.x] = s;
    __syncthreads();
    for (int st = 128; st > 0; st >>= 1) {
        if (threadIdx.x < st) red[threadIdx.x] += red[threadIdx.x + st];
        __syncthreads();
    }
    if (threadIdx.x == 0) d_Wsum[o] = red[0];
}

// ---------------- K3: ROI adaptive max pool 2x2 + ReLU ----------------
__global__ void k_roipool(const float* __restrict__ rois) {
    int bn = blockIdx.x;            // b*NR + n
    int b = bn / NR;
    const float* r = rois + bn * 4;
    float y1 = r[0] * 0.25f, x1 = r[1] * 0.25f;
    float y2 = r[2] * 0.25f, x2 = r[3] * 0.25f;
    int r0 = (int)truncf(y1), r1 = (int)truncf(x1);
    int r2 = (int)ceilf(y2),  r3 = (int)ceilf(x2);
    int hs = r2 - r0 + 1, ws = r3 - r1 + 1;
    int eh0 = r0 + (hs + 1) / 2;    // row region0: [r0, eh0)
    int sh1 = r0 + hs / 2;          // row region1: [sh1, r2]
    int ew0 = r1 + (ws + 1) / 2;    // col region0: [r1, ew0)
    int sw1 = r1 + ws / 2;          // col region1: [sw1, r3]

    int c = threadIdx.x;            // 512 threads = C
    float m00 = -FLT_MAX, m01 = -FLT_MAX, m10 = -FLT_MAX, m11 = -FLT_MAX;

    for (int h = r0; h <= r2; h++) {
        bool in0 = h < eh0;
        bool in1 = h >= sh1;
        const float* base = d_feat_t + ((size_t)(b * HH + h) * WW) * CC + c;
        for (int w = r1; w <= r3; w++) {
            float v = base[(size_t)w * CC];
            bool c0 = w < ew0;
            bool c1 = w >= sw1;
            if (in0 && c0) m00 = fmaxf(m00, v);
            if (in0 && c1) m01 = fmaxf(m01, v);
            if (in1 && c0) m10 = fmaxf(m10, v);
            if (in1 && c1) m11 = fmaxf(m11, v);
        }
    }
    float* out = d_pooled + (size_t)bn * F_IN + c * 4;
    out[0] = fmaxf(m00, 0.f);
    out[1] = fmaxf(m01, 0.f);
    out[2] = fmaxf(m10, 0.f);
    out[3] = fmaxf(m11, 0.f);
}

// ---------------- K4: per-n BN1 stats -> folded affine coeffs ----------------
__global__ void k_stats1(const float* __restrict__ gamma1,
                         const float* __restrict__ beta1) {
    int n = blockIdx.x;             // 180 blocks, 256 threads
    float s = 0.f, sq = 0.f;
    for (int i = threadIdx.x; i < BB * F_IN; i += 256) {
        int b = i / F_IN, f = i - b * F_IN;
        float v = d_pooled[((size_t)(b * NR + n)) * F_IN + f];
        s += v;
        sq += v * v;
    }
    __shared__ float rs[256], rq[256];
    rs[threadIdx.x] = s;
    rq[threadIdx.x] = sq;
    __syncthreads();
    for (int st = 128; st > 0; st >>= 1) {
        if (threadIdx.x < st) {
            rs[threadIdx.x] += rs[threadIdx.x + st];
            rq[threadIdx.x] += rq[threadIdx.x + st];
        }
        __syncthreads();
    }
    if (threadIdx.x == 0) {
        const float inv = 1.0f / (BB * F_IN);
        float mean = rs[0] * inv;
        float var = rq[0] * inv - mean * mean;
        float a = gamma1[n] * rsqrtf(var + EPSV);
        d_a1[n] = a;
        d_c1[n] = beta1[n] - a * mean;
    }
}

// ---------------- K5: GEMM g[b,n,o] = sum_f pooled[b,n,f] * W1[o,f] ----------------
// grid: B * (NR/4) blocks, 256 threads; each block does 4 ROIs.
__global__ void k_gemm() {
    __shared__ float xs[4][F_IN];          // 32KB
    __shared__ float part[4][4 * OO];      // [q][nl*64+o]
    int blk = blockIdx.x;
    int b = blk / (NR / 4);
    int n0 = (blk % (NR / 4)) * 4;

    for (int i = threadIdx.x; i < 4 * F_IN; i += 256) {
        int nl = i / F_IN, f = i - nl * F_IN;
        xs[nl][f] = d_pooled[((size_t)(b * NR + n0 + nl)) * F_IN + f];
    }
    __syncthreads();

    int o = threadIdx.x & 63;
    int q = threadIdx.x >> 6;              // f-quarter
    float a0 = 0.f, a1 = 0.f, a2 = 0.f, a3 = 0.f;
    int fbeg = q * (F_IN / 4);
    #pragma unroll 4
    for (int f = fbeg; f < fbeg + F_IN / 4; f++) {
        float wv = d_W1t[f * OO + o];
        a0 = fmaf(xs[0][f], wv, a0);
        a1 = fmaf(xs[1][f], wv, a1);
        a2 = fmaf(xs[2][f], wv, a2);
        a3 = fmaf(xs[3][f], wv, a3);
    }
    part[q][0 * OO + o] = a0;
    part[q][1 * OO + o] = a1;
    part[q][2 * OO + o] = a2;
    part[q][3 * OO + o] = a3;
    __syncthreads();

    // t -> (nl, o): sum over the 4 quarters
    int nl = threadIdx.x >> 6;
    float g = part[0][nl * OO + o] + part[1][nl * OO + o] +
              part[2][nl * OO + o] + part[3][nl * OO + o];
    d_g[((size_t)(b * NR + n0 + nl)) * OO + o] = g;
}

// ---------------- K6: apply folded BN1 affine + bias, BN2, write out ----------------
__global__ void k_final(const float* __restrict__ bl1,
                        const float* __restrict__ gamma2,
                        const float* __restrict__ beta2,
                        float* __restrict__ out) {
    int n = blockIdx.x;             // 180 blocks, 256 threads
    int t = threadIdx.x;
    int b = t >> 6, o = t & 63;
    float y = d_a1[n] * d_g[((size_t)(b * NR + n)) * OO + o]
            + d_c1[n] * d_Wsum[o] + bl1[o];

    __shared__ float rs[256], rq[256];
    rs[t] = y;
    rq[t] = y * y;
    __syncthreads();
    for (int st = 128; st > 0; st >>= 1) {
        if (t < st) {
            rs[t] += rs[t + st];
            rq[t] += rq[t + st];
        }
        __syncthreads();
    }
    float mean = rs[0] * (1.0f / 256.0f);
    float var = rq[0] * (1.0f / 256.0f) - mean * mean;
    out[((size_t)(b * NR + n)) * OO + o] =
        (y - mean) * rsqrtf(var + EPSV) * gamma2[n] + beta2[n];
}

// ---------------- launch ----------------
extern "C" void kernel_launch(void* const* d_in, const int* in_sizes, int n_in,
                              void* d_out, int out_size) {
    const float* features = (const float*)d_in[0];
    const float* rois     = (const float*)d_in[1];
    const float* gamma1   = (const float*)d_in[2];
    const float* beta1    = (const float*)d_in[3];
    const float* W1       = (const float*)d_in[4];
    const float* bl1      = (const float*)d_in[5];
    const float* gamma2   = (const float*)d_in[6];
    const float* beta2    = (const float*)d_in[7];
    float* out = (float*)d_out;

    dim3 tgrid((WW + 31) / 32, (CC + 31) / 32, BB * HH);
    k_transpose<<<tgrid, dim3(32, 8)>>>(features);
    k_prep_w1<<<OO, 256>>>(W1);
    k_roipool<<<BB * NR, CC>>>(rois);
    k_stats1<<<NR, 256>>>(gamma1, beta1);
    k_gemm<<<BB * (NR / 4), 256>>>();
    k_final<<<NR, 256>>>(bl1, gamma2, beta2, out);
}

// round 2
// speedup vs baseline: 2.6138x; 2.6138x over previous
#include <cuda_runtime.h>
#include <float.h>

#define BB 4
#define NR 180
#define CC 512
#define HH 48
#define WW 48
#define F_IN 2048
#define OO 64
#define EPSV 1e-5f
#define C4 (CC/4)        // 128 float4 per (h,w)
#define MT 12            // ROIs per gemm tile (15 tiles * 12 = 180)
#define KSPLIT 4
#define KQ (F_IN/KSPLIT) // 512

// ---------------- device scratch ----------------
__device__ float d_feat_t[BB * HH * WW * CC];   // [B,H,W,C]
__device__ float d_pooled[BB * NR * F_IN];      // relu'd pooled
__device__ float d_W1t[F_IN * OO];              // W1 transposed [F,O]
__device__ float d_Wsum[OO];                    // sum_f W1[o,f]
__device__ float d_s1[NR];                      // per-n sum of relu'd x over (b,f)
__device__ float d_s2[NR];                      // per-n sumsq
__device__ float d_g[BB * NR * OO];             // GEMM partial-sum target

__device__ __forceinline__ void max4(float4& a, const float4& b) {
    a.x = fmaxf(a.x, b.x); a.y = fmaxf(a.y, b.y);
    a.z = fmaxf(a.z, b.z); a.w = fmaxf(a.w, b.w);
}

// ---------------- K0: zero accumulators ----------------
__global__ void k_zero() {
    int i = blockIdx.x * 256 + threadIdx.x;
    if (i < BB * NR * OO) d_g[i] = 0.f;
    if (i < NR) { d_s1[i] = 0.f; d_s2[i] = 0.f; }
}

// ---------------- K1: features [B,C,H,W] -> [B,H,W,C] ----------------
__global__ void k_transpose(const float* __restrict__ feat) {
    __shared__ float tile[32][33];
    int bh = blockIdx.z;
    int b = bh / HH, h = bh % HH;
    int c0 = blockIdx.y * 32;
    int w0 = blockIdx.x * 32;
    #pragma unroll
    for (int k = 0; k < 32; k += 8) {
        int c = c0 + threadIdx.y + k;
        int w = w0 + threadIdx.x;
        if (w < WW)
            tile[threadIdx.y + k][threadIdx.x] = feat[((b * CC + c) * HH + h) * WW + w];
    }
    __syncthreads();
    #pragma unroll
    for (int k = 0; k < 32; k += 8) {
        int w = w0 + threadIdx.y + k;
        int c = c0 + threadIdx.x;
        if (w < WW)
            d_feat_t[(bh * WW + w) * CC + c] = tile[threadIdx.x][threadIdx.y + k];
    }
}

// ---------------- K2: W1 transpose + row sums ----------------
__global__ void k_prep_w1(const float* __restrict__ W1) {
    int o = blockIdx.x;
    float s = 0.f;
    for (int f = threadIdx.x; f < F_IN; f += 256) {
        float v = W1[o * F_IN + f];
        d_W1t[f * OO + o] = v;
        s += v;
    }
    __shared__ float red[256];
    red[threadIdx.x] = s;
    __syncthreads();
    for (int st = 128; st > 0; st >>= 1) {
        if (threadIdx.x < st) red[threadIdx.x] += red[threadIdx.x + st];
        __syncthreads();
    }
    if (threadIdx.x == 0) d_Wsum[o] = red[0];
}

// ---------------- K3: ROI adaptive max pool 2x2 + ReLU + BN1 partial stats --------
// 256 threads: cq = tid&127 (4 channels via float4), hp = tid>>7 (row parity).
__global__ void __launch_bounds__(256) k_roipool(const float* __restrict__ rois) {
    int bn = blockIdx.x;
    int b = bn / NR;
    const float* r = rois + bn * 4;
    float y1 = r[0] * 0.25f, x1 = r[1] * 0.25f;
    float y2 = r[2] * 0.25f, x2 = r[3] * 0.25f;
    int r0 = (int)truncf(y1), r1 = (int)truncf(x1);
    int r2 = (int)ceilf(y2),  r3 = (int)ceilf(x2);
    int hs = r2 - r0 + 1, ws = r3 - r1 + 1;
    int eh0 = r0 + (hs + 1) / 2;    // row region0: [r0, eh0)
    int sh1 = r0 + hs / 2;          // row region1: [sh1, r2]
    int ew0 = r1 + (ws + 1) / 2;    // col region0: [r1, ew0)
    int sw1 = r1 + ws / 2;          // col region1: [sw1, r3]

    int tid = threadIdx.x;
    int cq = tid & 127;
    int hp = tid >> 7;

    const float4 NEG = make_float4(-FLT_MAX, -FLT_MAX, -FLT_MAX, -FLT_MAX);
    float4 m00 = NEG, m01 = NEG, m10 = NEG, m11 = NEG;

    const float4* ft = (const float4*)d_feat_t;
    for (int h = r0 + hp; h <= r2; h += 2) {
        bool in0 = h < eh0;
        bool in1 = h >= sh1;
        const float4* row = ft + (b * HH + h) * (WW * C4) + cq;
        float4 rm0 = NEG, rm1 = NEG;
        int w = r1;
        float4 v = row[w * C4];
        for (; w < r3; w++) {
            float4 vn = row[(w + 1) * C4];   // prefetch next (MLP=2)
            if (w < ew0)  max4(rm0, v);
            if (w >= sw1) max4(rm1, v);
            v = vn;
        }
        // w == r3: always in region1; region0 only if r3 < ew0 (ws==1)
        if (r3 < ew0) max4(rm0, v);
        max4(rm1, v);
        if (in0) { max4(m00, rm0); max4(m01, rm1); }
        if (in1) { max4(m10, rm0); max4(m11, rm1); }
    }

    // merge the two h-halves
    __shared__ float4 sm[4][128];
    __shared__ float rs[128], rq[128];
    if (hp == 1) {
        sm[0][cq] = m00; sm[1][cq] = m01; sm[2][cq] = m10; sm[3][cq] = m11;
    }
    __syncthreads();
    if (hp == 0) {
        max4(m00, sm[0][cq]); max4(m01, sm[1][cq]);
        max4(m10, sm[2][cq]); max4(m11, sm[3][cq]);
        // ReLU
        const float4 Z = make_float4(0.f, 0.f, 0.f, 0.f);
        max4(m00, Z); max4(m01, Z); max4(m10, Z); max4(m11, Z);
        // write: channel c=4cq+j -> out[(4cq+j)*4 + k], k in {00,01,10,11}
        float4* out = (float4*)(d_pooled + (size_t)bn * F_IN + cq * 16);
        float4 o0 = make_float4(m00.x, m01.x, m10.x, m11.x);
        float4 o1 = make_float4(m00.y, m01.y, m10.y, m11.y);
        float4 o2 = make_float4(m00.z, m01.z, m10.z, m11.z);
        float4 o3 = make_float4(m00.w, m01.w, m10.w, m11.w);
        out[0] = o0; out[1] = o1; out[2] = o2; out[3] = o3;
        // partial BN1 stats for this (b,n): sum over its 2048 outputs
        float s = (o0.x + o0.y + o0.z + o0.w) + (o1.x + o1.y + o1.z + o1.w)
                + (o2.x + o2.y + o2.z + o2.w) + (o3.x + o3.y + o3.z + o3.w);
        float q = o0.x*o0.x + o0.y*o0.y + o0.z*o0.z + o0.w*o0.w
                + o1.x*o1.x + o1.y*o1.y + o1.z*o1.z + o1.w*o1.w
                + o2.x*o2.x + o2.y*o2.y + o2.z*o2.z + o2.w*o2.w
                + o3.x*o3.x + o3.y*o3.y + o3.z*o3.z + o3.w*o3.w;
        rs[cq] = s; rq[cq] = q;
    }
    __syncthreads();
    if (hp == 0) {
        for (int st = 64; st > 0; st >>= 1) {
            if (cq < st) { rs[cq] += rs[cq + st]; rq[cq] += rq[cq + st]; }
            __syncthreads();
        }
        if (cq == 0) {
            int n = bn % NR;
            atomicAdd(&d_s1[n], rs[0]);
            atomicAdd(&d_s2[n], rq[0]);
        }
    }
}

// ---------------- K4: GEMM, 12-ROI tiles x K/4 split, atomic combine ----------------
__global__ void __launch_bounds__(256) k_gemm() {
    __shared__ float xs[MT][KQ];            // 24KB
    int mb = blockIdx.x;                    // 0..59
    int b = mb / (NR / MT);
    int n0 = (mb % (NR / MT)) * MT;
    int k0 = blockIdx.y * KQ;

    int tid = threadIdx.x;
    for (int i = tid; i < MT * KQ; i += 256) {
        int nl = i >> 9, k = i & (KQ - 1);
        xs[nl][k] = d_pooled[((size_t)(b * NR + n0 + nl)) * F_IN + k0 + k];
    }
    __syncthreads();

    int o = tid & 63;
    int g = tid >> 6;                       // handles nl = 3g..3g+2
    float a0 = 0.f, a1 = 0.f, a2 = 0.f;
    const float* Wp = d_W1t + k0 * OO + o;
    #pragma unroll 8
    for (int k = 0; k < KQ; k++) {
        float wv = Wp[k * OO];
        a0 = fmaf(xs[3 * g + 0][k], wv, a0);
        a1 = fmaf(xs[3 * g + 1][k], wv, a1);
        a2 = fmaf(xs[3 * g + 2][k], wv, a2);
    }
    atomicAdd(&d_g[((size_t)(b * NR + n0 + 3 * g + 0)) * OO + o], a0);
    atomicAdd(&d_g[((size_t)(b * NR + n0 + 3 * g + 1)) * OO + o], a1);
    atomicAdd(&d_g[((size_t)(b * NR + n0 + 3 * g + 2)) * OO + o], a2);
}

// ---------------- K5: finalize BN1 affine + bias + BN2 + write ----------------
__global__ void k_final(const float* __restrict__ gamma1,
                        const float* __restrict__ beta1,
                        const float* __restrict__ bl1,
                        const float* __restrict__ gamma2,
                        const float* __restrict__ beta2,
                        float* __restrict__ out) {
    int n = blockIdx.x;
    int t = threadIdx.x;
    int b = t >> 6, o = t & 63;

    const float inv1 = 1.0f / (BB * F_IN);
    float mean1 = d_s1[n] * inv1;
    float var1 = d_s2[n] * inv1 - mean1 * mean1;
    float a1 = gamma1[n] * rsqrtf(var1 + EPSV);
    float c1 = beta1[n] - a1 * mean1;

    float y = a1 * d_g[((size_t)(b * NR + n)) * OO + o] + c1 * d_Wsum[o] + bl1[o];

    __shared__ float rs[256], rq[256];
    rs[t] = y;
    rq[t] = y * y;
    __syncthreads();
    for (int st = 128; st > 0; st >>= 1) {
        if (t < st) {
            rs[t] += rs[t + st];
            rq[t] += rq[t + st];
        }
        __syncthreads();
    }
    float mean = rs[0] * (1.0f / 256.0f);
    float var = rq[0] * (1.0f / 256.0f) - mean * mean;
    out[((size_t)(b * NR + n)) * OO + o] =
        (y - mean) * rsqrtf(var + EPSV) * gamma2[n] + beta2[n];
}

// ---------------- launch ----------------
extern "C" void kernel_launch(void* const* d_in, const int* in_sizes, int n_in,
                              void* d_out, int out_size) {
    const float* features = (const float*)d_in[0];
    const float* rois     = (const float*)d_in[1];
    const float* gamma1   = (const float*)d_in[2];
    const float* beta1    = (const float*)d_in[3];
    const float* W1       = (const float*)d_in[4];
    const float* bl1      = (const float*)d_in[5];
    const float* gamma2   = (const float*)d_in[6];
    const float* beta2    = (const float*)d_in[7];
    float* out = (float*)d_out;

    k_zero<<<(BB * NR * OO + 255) / 256, 256>>>();
    dim3 tgrid((WW + 31) / 32, (CC + 31) / 32, BB * HH);
    k_transpose<<<tgrid, dim3(32, 8)>>>(features);
    k_prep_w1<<<OO, 256>>>(W1);
    k_roipool<<<BB * NR, 256>>>(rois);
    dim3 ggrid(BB * (NR / MT), KSPLIT);
    k_gemm<<<ggrid, 256>>>();
    k_final<<<NR, 256>>>(gamma1, beta1, bl1, gamma2, beta2, out);
}